// round 15
// baseline (speedup 1.0000x reference)
#include <cuda_runtime.h>
#include <math.h>
#include <stdint.h>

#define Bb 128
#define Ss 1024
#define Dd 512
#define Nn 784

#define NSPLIT 2
#define COLS_PER (Nn / NSPLIT)   // 392
#define NFULL 24                 // full 16-col tiles per half + 8-col tail
#define GRIDSZ 256
#define THREADS 256
#define KSPLIT 16                // q-GEMM split-K factor
#define USPLIT 16                // u split factor
#define OSPLIT 8                 // out-GEMM split-K factor

// ---------------- scratch (no allocations allowed) ----------------
__device__ float g_qpart[KSPLIT * Bb * Dd];    // q split-K partials (4 MB)
__device__ float g_upart[USPLIT * 2 * Dd];     // u partials
__device__ float g_pacc[NSPLIT * Bb * Dd];     // unnormalized pooled partials
__device__ float g_mz[NSPLIT * Bb * 2];        // per-half (m, Z)
__device__ unsigned long long g_bar = 0ULL;    // monotonic grid barrier (never reset)

// ---------------- grid barrier: monotonic counter, replay-safe ----------------
__device__ __forceinline__ void grid_sync() {
    __syncthreads();
    if (threadIdx.x == 0) {
        __threadfence();  // release: all our global writes visible before arrival
        unsigned long long arrival = atomicAdd(&g_bar, 1ULL);
        unsigned long long goal = (arrival / GRIDSZ + 1ULL) * GRIDSZ;
        while (atomicAdd(&g_bar, 0ULL) < goal) __nanosleep(64);
    }
    __syncthreads();
}

// ================= single fused kernel: prep -> attn -> out-GEMM =================
__global__ __launch_bounds__(THREADS, 2) void fused_kernel(
    const float* __restrict__ in_state,  // [B,S]
    const float* __restrict__ image,     // [B,D,N]
    const float* __restrict__ Wq,        // [D,S]
    const float* __restrict__ bq,        // [D]
    const float* __restrict__ Wa,        // [D]
    const float* __restrict__ Wc,        // [D,2D]
    const float* __restrict__ Wo,        // [S,D]
    const float* __restrict__ bo,        // [S]
    float* __restrict__ out) {           // [B,S]
    __shared__ float As[16][72];
    __shared__ float Bs[16][72];
    __shared__ float spart[2][192];
    __shared__ float sf0[64], sf1[64];

    const int cta = blockIdx.x;   // 0..255
    const int tid = threadIdx.x;  // 0..255
    const int lane = tid & 31;
    const int warp = tid >> 5;

    // ======================= PHASE 0: prep =======================
    {
        const int z  = cta >> 4;           // 0..15
        const int g  = cta & 15;
        const int gx = g & 7;
        const int gy = g >> 3;
        const int tx = tid & 15, ty = tid >> 4;
        const int row0 = gy * 64, col0 = gx * 64;
        const int kbeg = z * (Ss / KSPLIT);   // 64 k per slice
        const int lm = tid >> 2;
        const int lk = (tid & 3) * 4;
        float a00=0,a01=0,a02=0,a03=0, a10=0,a11=0,a12=0,a13=0;
        float a20=0,a21=0,a22=0,a23=0, a30=0,a31=0,a32=0,a33=0;

        const float* arow = &in_state[(size_t)(row0 + lm) * Ss + kbeg + lk];
        const float* brow = &Wq[(size_t)(col0 + lm) * Ss + kbeg + lk];
        float4 av[4], bv[4];
#pragma unroll
        for (int i = 0; i < 4; i++) {
            av[i] = *(const float4*)(arow + i * 16);
            bv[i] = *(const float4*)(brow + i * 16);
        }
#pragma unroll
        for (int it = 0; it < 4; it++) {
            if (it) __syncthreads();
            As[lk + 0][lm] = av[it].x; As[lk + 1][lm] = av[it].y;
            As[lk + 2][lm] = av[it].z; As[lk + 3][lm] = av[it].w;
            Bs[lk + 0][lm] = bv[it].x; Bs[lk + 1][lm] = bv[it].y;
            Bs[lk + 2][lm] = bv[it].z; Bs[lk + 3][lm] = bv[it].w;
            __syncthreads();
#pragma unroll
            for (int kk = 0; kk < 16; kk++) {
                float4 a4 = *(float4*)&As[kk][ty * 4];
                float4 b4 = *(float4*)&Bs[kk][tx * 4];
                a00 += a4.x*b4.x; a01 += a4.x*b4.y; a02 += a4.x*b4.z; a03 += a4.x*b4.w;
                a10 += a4.y*b4.x; a11 += a4.y*b4.y; a12 += a4.y*b4.z; a13 += a4.y*b4.w;
                a20 += a4.z*b4.x; a21 += a4.z*b4.y; a22 += a4.z*b4.z; a23 += a4.z*b4.w;
                a30 += a4.w*b4.x; a31 += a4.w*b4.y; a32 += a4.w*b4.z; a33 += a4.w*b4.w;
            }
        }
        float* base = g_qpart + (size_t)z * Bb * Dd + (size_t)(row0 + ty * 4) * Dd + col0 + tx * 4;
        *(float4*)(base + 0 * Dd) = make_float4(a00, a01, a02, a03);
        *(float4*)(base + 1 * Dd) = make_float4(a10, a11, a12, a13);
        *(float4*)(base + 2 * Dd) = make_float4(a20, a21, a22, a23);
        *(float4*)(base + 3 * Dd) = make_float4(a30, a31, a32, a33);

        if (cta < 64) {
            const int col = (cta & 3) * 256 + tid;
            const int dbeg = (cta >> 2) * 32;
            float acc = 0.f;
#pragma unroll
            for (int d = dbeg; d < dbeg + 32; d++)
                acc += Wa[d] * Wc[(size_t)d * (2 * Dd) + col];
            g_upart[(cta >> 2) * (2 * Dd) + col] = acc;
        } else if (cta < 192) {
            const int j4 = (cta - 64) * 256 + tid;
            const float4 bvv = *(const float4*)&bo[(j4 * 4) & (Ss - 1)];
            *(float4*)&out[j4 * 4] = bvv;
        }
    }

    grid_sync();

    // ======================= PHASE 1: flash attention (3-deep pipeline) =======================
    {
        const int b = cta >> 1;
        const int c = cta & 1;
        const int d0 = warp * 64;
        const int r = lane >> 2;             // 0..7
        const int k = lane & 3;              // 0..3
        const float* imgb = image + (size_t)b * Dd * Nn + (size_t)c * COLS_PER;
        const float4* p0 = reinterpret_cast<const float4*>(imgb + (size_t)(d0 + r) * Nn) + k;

        const int dg0 = d0 + lane, dg1 = d0 + 32 + lane;
        float q0 = 0.f, q1 = 0.f, u10 = 0.f, u11 = 0.f, u20 = 0.f, u21 = 0.f;
#pragma unroll
        for (int p = 0; p < KSPLIT; p++) {
            q0 += g_qpart[((size_t)p * Bb + b) * Dd + dg0];
            q1 += g_qpart[((size_t)p * Bb + b) * Dd + dg1];
        }
#pragma unroll
        for (int p = 0; p < USPLIT; p++) {
            u10 += g_upart[p * (2 * Dd) + dg0];
            u11 += g_upart[p * (2 * Dd) + dg1];
            u20 += g_upart[p * (2 * Dd) + Dd + dg0];
            u21 += g_upart[p * (2 * Dd) + Dd + dg1];
        }
        const float swv0 = u10 * (q0 + bq[dg0]) + u20;
        const float swv1 = u11 * (q1 + bq[dg1]) + u21;

        float4 ra[8], rb[8], rc[8];
        float acc[8];                         // per-lane, columns pre-reduced per tile
#pragma unroll
        for (int j = 0; j < 8; j++) acc[j] = 0.f;
        float m = -INFINITY, Zl = 0.f;

#define LOADF(T, REG)                                                              \
    {                                                                              \
        _Pragma("unroll")                                                          \
        for (int j = 0; j < 8; j++) REG[j] = __ldg(&p0[(size_t)j * 1568 + (T) * 4]);\
    }
#define LOADT(REG)                                                                 \
    {                                                                              \
        _Pragma("unroll")                                                          \
        for (int j = 0; j < 8; j++)                                                \
            REG[j] = (k < 2) ? __ldg(&p0[(size_t)j * 1568 + 96])                   \
                             : make_float4(0.f, 0.f, 0.f, 0.f);                    \
    }
#define PROC(REG, PAR, TAILF)                                                      \
    {                                                                              \
        float4 s4 = make_float4(0.f, 0.f, 0.f, 0.f);                               \
        _Pragma("unroll")                                                          \
        for (int j = 0; j < 4; j++) {                                              \
            float wj = __shfl_sync(0xffffffffu, swv0, 8 * j + r);                  \
            s4.x += wj * REG[j].x; s4.y += wj * REG[j].y;                          \
            s4.z += wj * REG[j].z; s4.w += wj * REG[j].w;                          \
        }                                                                          \
        _Pragma("unroll")                                                          \
        for (int j = 4; j < 8; j++) {                                              \
            float wj = __shfl_sync(0xffffffffu, swv1, 8 * (j - 4) + r);            \
            s4.x += wj * REG[j].x; s4.y += wj * REG[j].y;                          \
            s4.z += wj * REG[j].z; s4.w += wj * REG[j].w;                          \
        }                                                                          \
        _Pragma("unroll")                                                          \
        for (int o = 4; o <= 16; o <<= 1) {                                        \
            s4.x += __shfl_xor_sync(0xffffffffu, s4.x, o);                         \
            s4.y += __shfl_xor_sync(0xffffffffu, s4.y, o);                         \
            s4.z += __shfl_xor_sync(0xffffffffu, s4.z, o);                         \
            s4.w += __shfl_xor_sync(0xffffffffu, s4.w, o);                         \
        }                                                                          \
        if (lane < 4) *(float4*)&spart[PAR][warp * 20 + lane * 4] = s4;            \
        __syncthreads();                                                           \
        float v = 0.f;                                                             \
        _Pragma("unroll")                                                          \
        for (int rr = 0; rr < 8; rr++) v += spart[PAR][rr * 20 + lane];            \
        const bool actv = (TAILF) ? (lane < 8) : (lane < 16);                      \
        float vm = actv ? v : -INFINITY;                                           \
        _Pragma("unroll")                                                          \
        for (int o = 16; o; o >>= 1)                                               \
            vm = fmaxf(vm, __shfl_xor_sync(0xffffffffu, vm, o));                   \
        float newm = fmaxf(m, vm);                                                 \
        float e = actv ? __expf(v - newm) : 0.f;                                   \
        float ts = e;                                                              \
        _Pragma("unroll")                                                          \
        for (int o = 16; o; o >>= 1) ts += __shfl_xor_sync(0xffffffffu, ts, o);    \
        const bool resc = (newm > m);                                              \
        float sc = resc ? __expf(m - newm) : 1.f;                                  \
        Zl = Zl * sc + ts;                                                         \
        m = newm;                                                                  \
        float4 e4;                                                                 \
        e4.x = __shfl_sync(0xffffffffu, e, 4 * k);                                 \
        e4.y = __shfl_sync(0xffffffffu, e, 4 * k + 1);                             \
        e4.z = __shfl_sync(0xffffffffu, e, 4 * k + 2);                             \
        e4.w = __shfl_sync(0xffffffffu, e, 4 * k + 3);                             \
        if (resc) {                                                                \
            _Pragma("unroll")                                                      \
            for (int j = 0; j < 8; j++) {                                          \
                float dt = e4.x * REG[j].x + e4.y * REG[j].y +                     \
                           e4.z * REG[j].z + e4.w * REG[j].w;                      \
                acc[j] = acc[j] * sc + dt;                                         \
            }                                                                      \
        } else {                                                                   \
            _Pragma("unroll")                                                      \
            for (int j = 0; j < 8; j++) {                                          \
                acc[j] += e4.x * REG[j].x + e4.y * REG[j].y +                      \
                          e4.z * REG[j].z + e4.w * REG[j].w;                       \
            }                                                                      \
        }                                                                          \
    }

        // 3-buffer pipeline: loads lead consumption by 2 tiles (~2 PROC durations)
        LOADF(0, ra)
        LOADF(1, rb)
#pragma unroll
        for (int t = 0; t < NFULL; t += 3) {      // NFULL = 24 = 8 groups of 3
            LOADF(t + 2, rc)                      // t+2 <= 23: always a full tile
            PROC(ra, ((t) & 1), false)
            if (t + 3 < NFULL) { LOADF(t + 3, ra) } else { LOADT(ra) }  // t=21 -> tail
            PROC(rb, ((t + 1) & 1), false)
            if (t + 4 < NFULL) { LOADF(t + 4, rb) }
            PROC(rc, ((t + 2) & 1), false)
        }
        PROC(ra, 0, true)   // tail tile (index 24, parity 0)
#undef LOADF
#undef LOADT
#undef PROC

#pragma unroll
        for (int j = 0; j < 8; j++) {
            float h = acc[j];
            h += __shfl_xor_sync(0xffffffffu, h, 1);
            h += __shfl_xor_sync(0xffffffffu, h, 2);
            if (k == 0) g_pacc[((size_t)c * Bb + b) * Dd + d0 + 8 * j + r] = h;
        }
        if (warp == 0 && lane == 0) {
            g_mz[(c * Bb + b) * 2 + 0] = m;
            g_mz[(c * Bb + b) * 2 + 1] = Zl;
        }
    }

    grid_sync();

    // ======================= PHASE 2: out += merge(pacc) @ Wo^T =======================
    {
        const int gx = cta & 15;           // 16 col tiles (64 wide)
        const int gy = (cta >> 4) & 1;     // 2 row tiles (64 tall)
        const int z  = cta >> 5;           // 8 k slices (64 each)
        const int tx = tid & 15, ty = tid >> 4;
        const int row0 = gy * 64, col0 = gx * 64;
        const int kbeg = z * (Dd / OSPLIT);
        const int lm = tid >> 2;
        const int lk = (tid & 3) * 4;

        if (tid < 64) {
            const int b = row0 + tid;
            const float m1 = g_mz[(0 * Bb + b) * 2 + 0], z1 = g_mz[(0 * Bb + b) * 2 + 1];
            const float m2 = g_mz[(1 * Bb + b) * 2 + 0], z2 = g_mz[(1 * Bb + b) * 2 + 1];
            const float M = fmaxf(m1, m2);
            const float e1 = __expf(m1 - M), e2 = __expf(m2 - M);
            const float inv = 1.f / (z1 * e1 + z2 * e2);
            sf0[tid] = e1 * inv;
            sf1[tid] = e2 * inv;
        }

        const float* pa0row = &g_pacc[(size_t)(0 * Bb + row0 + lm) * Dd + kbeg + lk];
        const float* pa1row = &g_pacc[(size_t)(1 * Bb + row0 + lm) * Dd + kbeg + lk];
        const float* wbrow  = &Wo[(size_t)(col0 + lm) * Dd + kbeg + lk];

        float a00=0,a01=0,a02=0,a03=0, a10=0,a11=0,a12=0,a13=0;
        float a20=0,a21=0,a22=0,a23=0, a30=0,a31=0,a32=0,a33=0;

        float4 pa0n = *(const float4*)(pa0row);
        float4 pa1n = *(const float4*)(pa1row);
        float4 bvn  = *(const float4*)(wbrow);
        __syncthreads();  // sf0/sf1 ready
        const float f0 = sf0[lm], f1 = sf1[lm];

#pragma unroll
        for (int it = 0; it < 4; it++) {
            float4 pa0 = pa0n, pa1 = pa1n, bv = bvn;
            if (it < 3) {
                const int off = (it + 1) * 16;
                pa0n = *(const float4*)(pa0row + off);
                pa1n = *(const float4*)(pa1row + off);
                bvn  = *(const float4*)(wbrow + off);
            }
            if (it) __syncthreads();
            As[lk + 0][lm] = f0 * pa0.x + f1 * pa1.x;
            As[lk + 1][lm] = f0 * pa0.y + f1 * pa1.y;
            As[lk + 2][lm] = f0 * pa0.z + f1 * pa1.z;
            As[lk + 3][lm] = f0 * pa0.w + f1 * pa1.w;
            Bs[lk + 0][lm] = bv.x; Bs[lk + 1][lm] = bv.y;
            Bs[lk + 2][lm] = bv.z; Bs[lk + 3][lm] = bv.w;
            __syncthreads();
#pragma unroll
            for (int kk = 0; kk < 16; kk++) {
                float4 a4 = *(float4*)&As[kk][ty * 4];
                float4 b4 = *(float4*)&Bs[kk][tx * 4];
                a00 += a4.x*b4.x; a01 += a4.x*b4.y; a02 += a4.x*b4.z; a03 += a4.x*b4.w;
                a10 += a4.y*b4.x; a11 += a4.y*b4.y; a12 += a4.y*b4.z; a13 += a4.y*b4.w;
                a20 += a4.z*b4.x; a21 += a4.z*b4.y; a22 += a4.z*b4.z; a23 += a4.z*b4.w;
                a30 += a4.w*b4.x; a31 += a4.w*b4.y; a32 += a4.w*b4.z; a33 += a4.w*b4.w;
            }
        }
        float* base = out + (size_t)(row0 + ty * 4) * Ss + col0 + tx * 4;
        atomicAdd(base + 0 * Ss + 0, a00); atomicAdd(base + 0 * Ss + 1, a01);
        atomicAdd(base + 0 * Ss + 2, a02); atomicAdd(base + 0 * Ss + 3, a03);
        atomicAdd(base + 1 * Ss + 0, a10); atomicAdd(base + 1 * Ss + 1, a11);
        atomicAdd(base + 1 * Ss + 2, a12); atomicAdd(base + 1 * Ss + 3, a13);
        atomicAdd(base + 2 * Ss + 0, a20); atomicAdd(base + 2 * Ss + 1, a21);
        atomicAdd(base + 2 * Ss + 2, a22); atomicAdd(base + 2 * Ss + 3, a23);
        atomicAdd(base + 3 * Ss + 0, a30); atomicAdd(base + 3 * Ss + 1, a31);
        atomicAdd(base + 3 * Ss + 2, a32); atomicAdd(base + 3 * Ss + 3, a33);
    }
}

// ---------------- launcher (1 graph node) ----------------
extern "C" void kernel_launch(void* const* d_in, const int* in_sizes, int n_in,
                              void* d_out, int out_size) {
    const float* in_state = (const float*)d_in[0];  // [B, S]
    const float* image    = (const float*)d_in[1];  // [B, D, N]
    const float* Wq       = (const float*)d_in[2];  // [D, S]
    const float* bq       = (const float*)d_in[3];  // [D]
    const float* Wc       = (const float*)d_in[4];  // [D, 2D]
    // d_in[5] = bc (cancels in softmax)
    const float* Wa       = (const float*)d_in[6];  // [1, D]
    // d_in[7] = ba (cancels in softmax)
    const float* Wo       = (const float*)d_in[8];  // [S, D]
    const float* bo       = (const float*)d_in[9];  // [S]
    float* out = (float*)d_out;                     // [B, S]

    fused_kernel<<<GRIDSZ, THREADS>>>(in_state, image, Wq, bq, Wa, Wc, Wo, bo, out);
}